// round 7
// baseline (speedup 1.0000x reference)
#include <cuda_runtime.h>
#include <cuda_bf16.h>

// LSTMStateBufferCell:
//   pos[b]  = sum_s hidden_masks[s,b]            (pos in [0,S])
//   prev    = mod(pos-1, S+1)
//   stack_X = [init_X ; X]  (index 0 = init row)
//   out_h[b,:] = stack_h[prev]*a + stack_h[pos]*(1-a),  a = |op[b]|
//   out_c[b,:] = stack_c[prev]*a + stack_c[pos]*(1-a)
// Output: f32 [2, B, H] (hidden then cell).
//
// Fast path (S==1024, H==1024): one block per batch element, 1024 threads.
// Per-thread serial depth:
//   1 mask LDG -> shfl tree + 1 sync + smem partial sum
//   -> 1 float2 row LDG -> 1 float2 STG.
// Mapping (fixed from R6): half = tid>>9 selects hidden/cell (512 thr each),
// lane = tid&511 indexes the row's 512 float2 elements — exact coverage,
// no overflow. a in {0,1} => blend is a pure row select.

#define NTH 1024

__global__ __launch_bounds__(NTH)
void lstm_state_kernel_fast(
    const float* __restrict__ hiddens,
    const float* __restrict__ cells,
    const float* __restrict__ init_hidden,
    const float* __restrict__ init_cell,
    const int*   __restrict__ masks,
    const int*   __restrict__ op,
    float* __restrict__ out,
    int S, int B, int H)     // S==1024, H==1024
{
    const int b   = blockIdx.x;
    const int tid = threadIdx.x;

    // Independent of the mask chain — issue first.
    const float a  = fabsf((float)__ldg(&op[b]));
    const float na = 1.0f - a;

    // ---- pos[b]: exactly one mask load per thread (S == NTH) ----
    int local = __ldg(&masks[(size_t)tid * B + b]);

    #pragma unroll
    for (int off = 16; off > 0; off >>= 1)
        local += __shfl_down_sync(0xffffffffu, local, off);

    __shared__ int wsum[NTH / 32];
    if ((tid & 31) == 0) wsum[tid >> 5] = local;
    __syncthreads();

    int pos = 0;
    #pragma unroll
    for (int w = 0; w < NTH / 32; w++) pos += wsum[w];

    const int prev = (pos == 0) ? S : pos - 1;   // mod(pos-1, S+1)

    // ---- Row select / blend: 512 threads per output, one float2 each ----
    const int half = tid >> 9;          // 0 = hidden, 1 = cell
    const int lane = tid & 511;         // float2 index in [0, 512) == H/2

    const size_t rowstride = (size_t)B * H;
    const float* data  = half ? cells     : hiddens;
    const float* initv = half ? init_cell : init_hidden;

    const float2* c2 = (const float2*)((pos  == 0) ? initv
                        : data + (size_t)(pos  - 1) * rowstride + (size_t)b * H);
    const float2* p2 = (const float2*)((prev == 0) ? initv
                        : data + (size_t)(prev - 1) * rowstride + (size_t)b * H);
    float2* d2 = (float2*)(out + (size_t)half * rowstride + (size_t)b * H);

    if (a == 1.0f) {
        d2[lane] = p2[lane];
    } else if (a == 0.0f) {
        d2[lane] = c2[lane];
    } else {
        float2 vp = p2[lane], vc = c2[lane], r;
        r.x = vp.x * a + vc.x * na;
        r.y = vp.y * a + vc.y * na;
        d2[lane] = r;
    }
}

// ---------------- Generic fallback (any S,B,H) — round-5 kernel ----------------
#define GTH 512

__global__ __launch_bounds__(GTH)
void lstm_state_kernel_generic(
    const float* __restrict__ hiddens,
    const float* __restrict__ cells,
    const float* __restrict__ init_hidden,
    const float* __restrict__ init_cell,
    const int*   __restrict__ masks,
    const int*   __restrict__ op,
    float* __restrict__ out,
    int S, int B, int H)
{
    const int b   = blockIdx.x;
    const int tid = threadIdx.x;

    const float a  = fabsf((float)op[b]);
    const float na = 1.0f - a;

    int local = 0;
    for (int s = tid; s < S; s += GTH)
        local += masks[(size_t)s * B + b];

    #pragma unroll
    for (int off = 16; off > 0; off >>= 1)
        local += __shfl_down_sync(0xffffffffu, local, off);

    __shared__ int wsum[GTH / 32];
    if ((tid & 31) == 0) wsum[tid >> 5] = local;
    __syncthreads();

    int pos = 0;
    #pragma unroll
    for (int w = 0; w < GTH / 32; w++) pos += wsum[w];

    const int prev = (pos == 0) ? S : pos - 1;

    const size_t rowstride = (size_t)B * H;
    const int half = tid >> 8;
    const int lane = tid & 255;

    const float* data  = half ? cells     : hiddens;
    const float* initv = half ? init_cell : init_hidden;
    const float* cur_row  = (pos  == 0) ? initv
                          : data + (size_t)(pos  - 1) * rowstride + (size_t)b * H;
    const float* prev_row = (prev == 0) ? initv
                          : data + (size_t)(prev - 1) * rowstride + (size_t)b * H;
    float* dst = out + (size_t)half * rowstride + (size_t)b * H;

    for (int i = lane; i < H; i += 256)
        dst[i] = prev_row[i] * a + cur_row[i] * na;
}

extern "C" void kernel_launch(void* const* d_in, const int* in_sizes, int n_in,
                              void* d_out, int out_size)
{
    const float* hiddens     = (const float*)d_in[0];
    const float* cells       = (const float*)d_in[1];
    const float* init_hidden = (const float*)d_in[2];
    const float* init_cell   = (const float*)d_in[3];
    const int*   masks       = (const int*)d_in[4];
    const int*   op          = (const int*)d_in[5];
    float*       out         = (float*)d_out;

    const int H = in_sizes[2];          // init_hidden length
    const int B = in_sizes[5];          // op length
    const int S = in_sizes[4] / B;      // masks is [S,B]

    if (S == 1024 && H == 1024) {
        lstm_state_kernel_fast<<<B, NTH>>>(hiddens, cells, init_hidden, init_cell,
                                           masks, op, out, S, B, H);
    } else {
        lstm_state_kernel_generic<<<B, GTH>>>(hiddens, cells, init_hidden, init_cell,
                                              masks, op, out, S, B, H);
    }
}